// round 1
// baseline (speedup 1.0000x reference)
#include <cuda_runtime.h>
#include <math.h>

// Problem constants
#define B_   4
#define N_   4096
#define DIM_ 512
#define H_   8
#define DH_  64
#define M_   256
#define L_   16
#define KW_  33
#define BH_  32   // B_*H_

// ---------------- scratch (device globals; no allocations allowed) ----------
__device__ float g_q   [BH_*N_*DH_];
__device__ float g_k   [BH_*N_*DH_];
__device__ float g_v   [BH_*N_*DH_];
__device__ float g_qlm [BH_*M_*DH_];
__device__ float g_klm [BH_*M_*DH_];
__device__ float g_sim1[BH_*N_*M_];     // 33.5M floats
__device__ float g_attn2[BH_*M_*M_];
__device__ float g_sim3[BH_*M_*N_];     // 33.5M floats
__device__ float g_z   [BH_*M_*M_];
__device__ float g_z2  [BH_*M_*M_];
__device__ float g_xz  [BH_*M_*M_];
__device__ float g_t1  [BH_*M_*M_];
__device__ float g_t3  [BH_*M_*M_];
__device__ float g_t5  [BH_*M_*M_];
__device__ float g_a3v [BH_*M_*DH_];
__device__ float g_tmp [BH_*N_*M_];     // attn1 @ z
__device__ float g_o   [BH_*N_*DH_];
__device__ float g_of  [B_*N_*DIM_];
__device__ float g_gmax[2];

// ---------------- generic batched SGEMM -------------------------------------
// C[bz] = epilogue( A[bz](MxK) @ op(B[bz]) ), row-major, all dims multiples of tile.
// modes: 0: C = alpha*acc
//        2: C = dval*I - acc             (square matrices)
//        3: C = acc ; C2 = dval*I - acc  (dual output)
//        4: C = acc + bias[col]
//        5: qkv scatter: row=(b,n), col selects q/k/v + (h,d); q scaled by 0.125
#define BM 64
#define BN 64
#define BK 16

__global__ void __launch_bounds__(256)
sgemm(int M, int N, int K,
      const float* __restrict__ A, int lda, long long sA,
      const float* __restrict__ B, int ldb, long long sB, int transB,
      float* __restrict__ C, int ldc, long long sC,
      float alpha, int mode, float dval,
      float* __restrict__ C2, const float* __restrict__ bias,
      float* __restrict__ oq, float* __restrict__ ok_, float* __restrict__ ov)
{
    __shared__ float As[BK][BM];
    __shared__ float Bs[BK][BN];

    int bz = blockIdx.z;
    A += bz * sA;
    B += bz * sB;
    C += bz * sC;
    if (C2) C2 += bz * sC;

    int tid = threadIdx.x;
    int tx = tid & 15, ty = tid >> 4;
    int rowBase = blockIdx.y * BM;
    int colBase = blockIdx.x * BN;

    float acc[4][4];
#pragma unroll
    for (int i = 0; i < 4; i++)
#pragma unroll
        for (int j = 0; j < 4; j++) acc[i][j] = 0.f;

    int arow = tid >> 2;          // 0..63
    int akq  = (tid & 3) << 2;    // 0,4,8,12
    int bkk  = tid >> 4;          // 0..15  (!transB)
    int bnq  = (tid & 15) << 2;   // 0..60
    int tbn  = tid >> 2;          // 0..63  (transB)
    int tbkq = (tid & 3) << 2;

    for (int kt = 0; kt < K; kt += BK) {
        float4 av = *(const float4*)(A + (long long)(rowBase + arow) * lda + kt + akq);
        As[akq + 0][arow] = av.x;
        As[akq + 1][arow] = av.y;
        As[akq + 2][arow] = av.z;
        As[akq + 3][arow] = av.w;
        if (!transB) {
            float4 bv = *(const float4*)(B + (long long)(kt + bkk) * ldb + colBase + bnq);
            *(float4*)&Bs[bkk][bnq] = bv;
        } else {
            float4 bv = *(const float4*)(B + (long long)(colBase + tbn) * ldb + kt + tbkq);
            Bs[tbkq + 0][tbn] = bv.x;
            Bs[tbkq + 1][tbn] = bv.y;
            Bs[tbkq + 2][tbn] = bv.z;
            Bs[tbkq + 3][tbn] = bv.w;
        }
        __syncthreads();
#pragma unroll
        for (int kk = 0; kk < BK; kk++) {
            float a[4], b[4];
#pragma unroll
            for (int i = 0; i < 4; i++) a[i] = As[kk][ty + 16 * i];
#pragma unroll
            for (int j = 0; j < 4; j++) b[j] = Bs[kk][tx + 16 * j];
#pragma unroll
            for (int i = 0; i < 4; i++)
#pragma unroll
                for (int j = 0; j < 4; j++)
                    acc[i][j] = fmaf(a[i], b[j], acc[i][j]);
        }
        __syncthreads();
    }

#pragma unroll
    for (int i = 0; i < 4; i++) {
        int r = rowBase + ty + 16 * i;
#pragma unroll
        for (int j = 0; j < 4; j++) {
            int c = colBase + tx + 16 * j;
            float val = acc[i][j];
            long long idx = (long long)r * ldc + c;
            if (mode == 0) {
                C[idx] = alpha * val;
            } else if (mode == 2) {
                C[idx] = (r == c ? dval : 0.f) - val;
            } else if (mode == 3) {
                C[idx]  = val;
                C2[idx] = (r == c ? dval : 0.f) - val;
            } else if (mode == 4) {
                C[idx] = val + bias[c];
            } else { // 5: qkv scatter
                int b = r >> 12, n = r & 4095;
                int part = c >> 9, h = (c >> 6) & 7, d = c & 63;
                float* dst = (part == 0) ? oq : ((part == 1) ? ok_ : ov);
                if (part == 0) val *= 0.125f;  // DH^-0.5
                dst[(((long long)(b * 8 + h) << 12) + n) * 64 + d] = val;
            }
        }
    }
}

// ---------------- landmarks (window mean, l=16) ------------------------------
__global__ void landmarks_kernel(const float* __restrict__ q, const float* __restrict__ k,
                                 float* __restrict__ qlm, float* __restrict__ klm)
{
    int idx = blockIdx.x;          // bh*256 + m
    int d = threadIdx.x;           // 0..63
    long long base = ((long long)idx * 16) * 64 + d;   // (bh*4096 + m*16)*64 + d
    float sq = 0.f, sk = 0.f;
#pragma unroll
    for (int j = 0; j < 16; j++) {
        sq += q[base + j * 64];
        sk += k[base + j * 64];
    }
    qlm[(long long)idx * 64 + d] = sq * 0.0625f;
    klm[(long long)idx * 64 + d] = sk * 0.0625f;
}

// ---------------- row softmax -------------------------------------------------
__global__ void softmax_rows(float* __restrict__ data, int cols)
{
    __shared__ float red[256];
    long long row = blockIdx.x;
    float* p = data + row * cols;
    int tid = threadIdx.x;

    float m = -3.4e38f;
    for (int c = tid; c < cols; c += 256) m = fmaxf(m, p[c]);
    red[tid] = m; __syncthreads();
    for (int s = 128; s > 0; s >>= 1) {
        if (tid < s) red[tid] = fmaxf(red[tid], red[tid + s]);
        __syncthreads();
    }
    m = red[0]; __syncthreads();

    float sum = 0.f;
    for (int c = tid; c < cols; c += 256) {
        float e = __expf(p[c] - m);
        p[c] = e; sum += e;
    }
    red[tid] = sum; __syncthreads();
    for (int s = 128; s > 0; s >>= 1) {
        if (tid < s) red[tid] += red[tid + s];
        __syncthreads();
    }
    float inv = 1.f / red[0];
    for (int c = tid; c < cols; c += 256) p[c] *= inv;
}

// ---------------- pinv init ---------------------------------------------------
__global__ void zero_gmax(float* gm) { gm[0] = 0.f; gm[1] = 0.f; }

__global__ void pinv_scales(const float* __restrict__ a, float* gm)
{
    __shared__ float red[256];
    int bh = blockIdx.x, tid = threadIdx.x;
    const float* A = a + ((long long)bh << 16);
    float rs = 0.f;
    for (int j = 0; j < 256; j++) rs += fabsf(A[tid * 256 + j]);
    red[tid] = rs; __syncthreads();
    for (int s = 128; s > 0; s >>= 1) {
        if (tid < s) red[tid] = fmaxf(red[tid], red[tid + s]);
        __syncthreads();
    }
    if (tid == 0) atomicMax((int*)&gm[0], __float_as_int(red[0]));
    __syncthreads();
    float cs = 0.f;
    for (int i = 0; i < 256; i++) cs += fabsf(A[i * 256 + tid]);
    red[tid] = cs; __syncthreads();
    for (int s = 128; s > 0; s >>= 1) {
        if (tid < s) red[tid] = fmaxf(red[tid], red[tid + s]);
        __syncthreads();
    }
    if (tid == 0) atomicMax((int*)&gm[1], __float_as_int(red[0]));
}

__global__ void pinv_init(const float* __restrict__ a, float* __restrict__ z,
                          const float* __restrict__ gm)
{
    long long t = (long long)blockIdx.x * 256 + threadIdx.x;   // BH*256*256
    int bh = (int)(t >> 16);
    int ij = (int)(t & 65535);
    int i = ij >> 8, j = ij & 255;
    float inv = 1.f / (gm[0] * gm[1]);
    z[((long long)bh << 16) + ij] = a[((long long)bh << 16) + (j << 8) + i] * inv;
}

// ---------------- depthwise residual conv (cross-correlation, pad 16) --------
__global__ void conv_add(const float* __restrict__ v, const float* __restrict__ w,
                         float* __restrict__ out)
{
    long long t = (long long)blockIdx.x * 256 + threadIdx.x;   // BH*N*DH
    int d = (int)(t & 63);
    long long r = t >> 6;
    int n  = (int)(r & 4095);
    int bh = (int)(r >> 12);
    int h  = bh & 7;
    const float* vp = v + ((long long)bh << 18) + d;
    float s = 0.f;
#pragma unroll
    for (int tp = 0; tp < 33; tp++) {
        int nn = n + tp - 16;
        if (nn >= 0 && nn < 4096)
            s = fmaf(vp[(long long)nn << 6], w[h * 33 + tp], s);
    }
    out[t] += s;
}

// ---------------- [b,h,n,d] -> [b,n,h*64+d] -----------------------------------
__global__ void reorder_kernel(const float* __restrict__ o, float* __restrict__ of)
{
    long long t = (long long)blockIdx.x * 256 + threadIdx.x;   // B*N*DIM order [b,n,h,d]
    int d = (int)(t & 63);
    long long r = t >> 6;
    int h = (int)(r & 7);
    long long r2 = r >> 3;
    int n = (int)(r2 & 4095);
    int b = (int)(r2 >> 12);
    of[t] = o[(((long long)(b * 8 + h) << 12) + n) * 64 + d];
}

// ---------------- host orchestration ------------------------------------------
extern "C" void kernel_launch(void* const* d_in, const int* in_sizes, int n_in,
                              void* d_out, int out_size)
{
    const float* x    = (const float*)d_in[0];
    const float* Wqkv = (const float*)d_in[1];
    const float* Wout = (const float*)d_in[2];
    const float* bout = (const float*)d_in[3];
    const float* rk   = (const float*)d_in[4];
    float* yout = (float*)d_out;

    float *q, *k, *v, *qlm, *klm, *s1, *a2, *s3, *z, *z2, *xz, *t1, *t3, *t5,
          *a3v, *tmp, *o, *of, *gm;
    cudaGetSymbolAddress((void**)&q,   g_q);
    cudaGetSymbolAddress((void**)&k,   g_k);
    cudaGetSymbolAddress((void**)&v,   g_v);
    cudaGetSymbolAddress((void**)&qlm, g_qlm);
    cudaGetSymbolAddress((void**)&klm, g_klm);
    cudaGetSymbolAddress((void**)&s1,  g_sim1);
    cudaGetSymbolAddress((void**)&a2,  g_attn2);
    cudaGetSymbolAddress((void**)&s3,  g_sim3);
    cudaGetSymbolAddress((void**)&z,   g_z);
    cudaGetSymbolAddress((void**)&z2,  g_z2);
    cudaGetSymbolAddress((void**)&xz,  g_xz);
    cudaGetSymbolAddress((void**)&t1,  g_t1);
    cudaGetSymbolAddress((void**)&t3,  g_t3);
    cudaGetSymbolAddress((void**)&t5,  g_t5);
    cudaGetSymbolAddress((void**)&a3v, g_a3v);
    cudaGetSymbolAddress((void**)&tmp, g_tmp);
    cudaGetSymbolAddress((void**)&o,   g_o);
    cudaGetSymbolAddress((void**)&of,  g_of);
    cudaGetSymbolAddress((void**)&gm,  g_gmax);

    const long long sQ  = (long long)N_ * DH_;   // 262144
    const long long sLM = (long long)M_ * DH_;   // 16384
    const long long sS1 = (long long)N_ * M_;    // 1048576
    const long long sMM = (long long)M_ * M_;    // 65536

    // 1. qkv projection, scatter into q(scaled)/k/v [b,h,n,d]
    sgemm<<<dim3(1536 / BN, 16384 / BM, 1), 256>>>(
        16384, 1536, 512, x, 512, 0, Wqkv, 1536, 0, 0,
        q /*unused*/, 1536, 0, 1.f, 5, 0.f, nullptr, nullptr, q, k, v);

    // 2. landmarks
    landmarks_kernel<<<BH_ * M_, DH_>>>(q, k, qlm, klm);

    // 3. sim1 = q @ klm^T ; softmax
    sgemm<<<dim3(M_ / BN, N_ / BM, BH_), 256>>>(
        N_, M_, DH_, q, DH_, sQ, klm, DH_, sLM, 1,
        s1, M_, sS1, 1.f, 0, 0.f, nullptr, nullptr, nullptr, nullptr, nullptr);
    softmax_rows<<<BH_ * N_, 256>>>(s1, M_);

    // 4. sim2 = qlm @ klm^T ; softmax -> attn2
    sgemm<<<dim3(M_ / BN, M_ / BM, BH_), 256>>>(
        M_, M_, DH_, qlm, DH_, sLM, klm, DH_, sLM, 1,
        a2, M_, sMM, 1.f, 0, 0.f, nullptr, nullptr, nullptr, nullptr, nullptr);
    softmax_rows<<<BH_ * M_, 256>>>(a2, M_);

    // 5. sim3 = qlm @ k^T ; softmax -> attn3
    sgemm<<<dim3(N_ / BN, M_ / BM, BH_), 256>>>(
        M_, N_, DH_, qlm, DH_, sLM, k, DH_, sQ, 1,
        s3, N_, (long long)M_ * N_, 1.f, 0, 0.f, nullptr, nullptr, nullptr, nullptr, nullptr);
    softmax_rows<<<BH_ * M_, 256>>>(s3, N_);

    // 6. pinv init: z0 = attn2^T / (max(rowsum)*max(colsum))  (GLOBAL maxes)
    zero_gmax<<<1, 1>>>(gm);
    pinv_scales<<<BH_, 256>>>(a2, gm);
    pinv_init<<<(BH_ * M_ * M_) / 256, 256>>>(a2, z, gm);

    // 7. Newton-Schulz iterations
    float* za = z;
    float* zb = z2;
    for (int it = 0; it < 6; it++) {
        // xz = X @ Z ; t1 = 7I - xz
        sgemm<<<dim3(4, 4, BH_), 256>>>(256, 256, 256, a2, 256, sMM, za, 256, sMM, 0,
                                        xz, 256, sMM, 1.f, 3, 7.f, t1, nullptr,
                                        nullptr, nullptr, nullptr);
        // t3 = 15I - xz @ t1
        sgemm<<<dim3(4, 4, BH_), 256>>>(256, 256, 256, xz, 256, sMM, t1, 256, sMM, 0,
                                        t3, 256, sMM, 1.f, 2, 15.f, nullptr, nullptr,
                                        nullptr, nullptr, nullptr);
        // t5 = 13I - xz @ t3
        sgemm<<<dim3(4, 4, BH_), 256>>>(256, 256, 256, xz, 256, sMM, t3, 256, sMM, 0,
                                        t5, 256, sMM, 1.f, 2, 13.f, nullptr, nullptr,
                                        nullptr, nullptr, nullptr);
        // z' = 0.25 * Z @ t5
        sgemm<<<dim3(4, 4, BH_), 256>>>(256, 256, 256, za, 256, sMM, t5, 256, sMM, 0,
                                        zb, 256, sMM, 0.25f, 0, 0.f, nullptr, nullptr,
                                        nullptr, nullptr, nullptr);
        float* sw = za; za = zb; zb = sw;
    }

    // 8. a3v = attn3 @ v
    sgemm<<<dim3(DH_ / BN, M_ / BM, BH_), 256>>>(
        M_, DH_, N_, s3, N_, (long long)M_ * N_, v, DH_, sQ, 0,
        a3v, DH_, sLM, 1.f, 0, 0.f, nullptr, nullptr, nullptr, nullptr, nullptr);

    // 9. tmp = attn1 @ z
    sgemm<<<dim3(M_ / BN, N_ / BM, BH_), 256>>>(
        N_, M_, M_, s1, M_, sS1, za, M_, sMM, 0,
        tmp, M_, sS1, 1.f, 0, 0.f, nullptr, nullptr, nullptr, nullptr, nullptr);

    // 10. out = tmp @ a3v
    sgemm<<<dim3(DH_ / BN, N_ / BM, BH_), 256>>>(
        N_, DH_, M_, tmp, M_, sS1, a3v, DH_, sLM, 0,
        o, DH_, sQ, 1.f, 0, 0.f, nullptr, nullptr, nullptr, nullptr, nullptr);

    // 11. += depthwise conv of v
    conv_add<<<(BH_ * N_ * DH_) / 256, 256>>>(v, rk, o);

    // 12. reorder to [b, n, h*dh]
    reorder_kernel<<<(B_ * N_ * DIM_) / 256, 256>>>(o, of);

    // 13. final projection: y = of @ Wout + bout
    sgemm<<<dim3(512 / BN, 16384 / BM, 1), 256>>>(
        16384, 512, 512, of, 512, 0, Wout, 512, 0, 0,
        yout, 512, 0, 1.f, 4, 0.f, nullptr, bout, nullptr, nullptr, nullptr);
}

// round 2
// speedup vs baseline: 3.4007x; 3.4007x over previous
#include <cuda_runtime.h>
#include <stdint.h>
#include <math.h>

#define B_   4
#define N_   4096
#define DIM_ 512
#define H_   8
#define DH_  64
#define M_   256
#define BH_  32

// ---------------- scratch ----------------------------------------------------
__device__ float g_q  [BH_*N_*DH_];
__device__ float g_k  [BH_*N_*DH_];
__device__ float g_v  [BH_*N_*DH_];
__device__ float g_qlm[BH_*M_*DH_];
__device__ float g_klm[BH_*M_*DH_];
__device__ float g_s1 [BH_*N_*M_];
__device__ float g_a2 [BH_*M_*M_];
__device__ float g_s3 [BH_*M_*N_];
__device__ float g_z  [BH_*M_*M_];
__device__ float g_z2 [BH_*M_*M_];
__device__ float g_xz [BH_*M_*M_];
__device__ float g_t1 [BH_*M_*M_];
__device__ float g_t3 [BH_*M_*M_];
__device__ float g_t5 [BH_*M_*M_];
__device__ float g_a3v[BH_*M_*DH_];
__device__ float g_zv [BH_*M_*DH_];
__device__ float g_of [B_*N_*DIM_];
__device__ float g_gmax[2];

// ---------------- tf32 helpers -----------------------------------------------
__device__ __forceinline__ uint32_t f2tf(float f) {
    uint32_t u; asm("cvt.rna.tf32.f32 %0, %1;" : "=r"(u) : "f"(f)); return u;
}

__device__ __forceinline__ void mma_tf32(float c[4],
    uint32_t a0, uint32_t a1, uint32_t a2, uint32_t a3, uint32_t b0, uint32_t b1)
{
    asm("mma.sync.aligned.m16n8k8.row.col.f32.tf32.tf32.f32 "
        "{%0,%1,%2,%3}, {%4,%5,%6,%7}, {%8,%9}, {%0,%1,%2,%3};"
        : "+f"(c[0]), "+f"(c[1]), "+f"(c[2]), "+f"(c[3])
        : "r"(a0), "r"(a1), "r"(a2), "r"(a3), "r"(b0), "r"(b1));
}

// ---------------- tensor-core batched GEMM ------------------------------------
// C[bz] = epi( A[bz](MxK,row) @ op(B[bz]) )  — 256 threads, tile BM x BN x 16.
// MODE: 0: alpha*acc   2: dval*I - acc   3: C=acc, C2=dval*I-acc
//       4: acc + bias[col]   5: qkv scatter (q scaled 0.125)
//       6: write [b,n,h,d] 'of' layout from bz=(b,h)-batched GEMM
template<int BM, int BN, int WGM, int WGN, int TRANSB, int MODE>
__global__ void __launch_bounds__(256)
gemm_tc(int K,
        const float* __restrict__ A,  int lda, long long sA,
        const float* __restrict__ Bg, int ldb, long long sB,
        float* __restrict__ C, int ldc, long long sC,
        float alpha, float dval,
        float* __restrict__ C2, const float* __restrict__ bias,
        float* __restrict__ oq, float* __restrict__ okk, float* __restrict__ ov)
{
    constexpr int BK = 16;
    constexpr int WM = BM / WGM, WN = BN / WGN;
    constexpr int MI = WM / 16,  NI = WN / 8;
    constexpr int AI  = (BM * BK) / (256 * 4);
    constexpr int NQ  = BN / 4;
    constexpr int B0I = (BK * BN) / (256 * 4);
    constexpr int B0S = 256 / NQ;
    constexpr int B1I = BN / 64;
    constexpr int BI  = TRANSB ? B1I : B0I;

    __shared__ uint32_t As[BK * BM];
    __shared__ uint32_t Bs[BK * BN];

    const int bz = blockIdx.z;
    A  += (long long)bz * sA;
    Bg += (long long)bz * sB;
    if (MODE != 5 && MODE != 6) C += (long long)bz * sC;
    if (MODE == 3) C2 += (long long)bz * sC;

    const int tid = threadIdx.x;
    const int rowBase = blockIdx.y * BM;
    const int colBase = blockIdx.x * BN;
    const int w = tid >> 5, lane = tid & 31;
    const int wm = w / WGN, wn = w % WGN;
    const int tm = lane >> 2, lq = lane & 3;

    float acc[MI][NI][4];
#pragma unroll
    for (int mi = 0; mi < MI; mi++)
#pragma unroll
        for (int ni = 0; ni < NI; ni++)
#pragma unroll
            for (int r = 0; r < 4; r++) acc[mi][ni][r] = 0.f;

    const int a_k4 = (tid & 3) * 4;
    const int a_m  = tid >> 2;
    const int b0_n = (tid % NQ) * 4;
    const int b0_k = tid / NQ;
    const int b1_k4 = (tid & 3) * 4;
    const int b1_n  = tid >> 2;

    float4 aReg[AI];
    float4 bReg[BI];

    // prologue loads
#pragma unroll
    for (int i = 0; i < AI; i++)
        aReg[i] = *(const float4*)(A + (long long)(rowBase + a_m + 64 * i) * lda + a_k4);
    if (TRANSB == 0) {
#pragma unroll
        for (int i = 0; i < BI; i++)
            bReg[i] = *(const float4*)(Bg + (long long)(b0_k + B0S * i) * ldb + colBase + b0_n);
    } else {
#pragma unroll
        for (int i = 0; i < BI; i++)
            bReg[i] = *(const float4*)(Bg + (long long)(colBase + b1_n + 64 * i) * ldb + b1_k4);
    }

    for (int kt = 0; kt < K; kt += BK) {
        // stage to smem (tf32-round once here)
#pragma unroll
        for (int i = 0; i < AI; i++) {
            int m = a_m + 64 * i;
            As[(a_k4 + 0) * BM + (m ^ 0 )] = f2tf(aReg[i].x);
            As[(a_k4 + 1) * BM + (m ^ 8 )] = f2tf(aReg[i].y);
            As[(a_k4 + 2) * BM + (m ^ 16)] = f2tf(aReg[i].z);
            As[(a_k4 + 3) * BM + (m ^ 24)] = f2tf(aReg[i].w);
        }
        if (TRANSB == 0) {
#pragma unroll
            for (int i = 0; i < BI; i++) {
                int k = b0_k + B0S * i;
                uint4 u;
                u.x = f2tf(bReg[i].x); u.y = f2tf(bReg[i].y);
                u.z = f2tf(bReg[i].z); u.w = f2tf(bReg[i].w);
                *(uint4*)&Bs[k * BN + (b0_n ^ ((k & 3) << 3))] = u;
            }
        } else {
#pragma unroll
            for (int i = 0; i < BI; i++) {
                int n = b1_n + 64 * i;
                Bs[(b1_k4 + 0) * BN + (n ^ 0 )] = f2tf(bReg[i].x);
                Bs[(b1_k4 + 1) * BN + (n ^ 8 )] = f2tf(bReg[i].y);
                Bs[(b1_k4 + 2) * BN + (n ^ 16)] = f2tf(bReg[i].z);
                Bs[(b1_k4 + 3) * BN + (n ^ 24)] = f2tf(bReg[i].w);
            }
        }
        __syncthreads();

        // prefetch next tile
        if (kt + BK < K) {
            int kn = kt + BK;
#pragma unroll
            for (int i = 0; i < AI; i++)
                aReg[i] = *(const float4*)(A + (long long)(rowBase + a_m + 64 * i) * lda + kn + a_k4);
            if (TRANSB == 0) {
#pragma unroll
                for (int i = 0; i < BI; i++)
                    bReg[i] = *(const float4*)(Bg + (long long)(kn + b0_k + B0S * i) * ldb + colBase + b0_n);
            } else {
#pragma unroll
                for (int i = 0; i < BI; i++)
                    bReg[i] = *(const float4*)(Bg + (long long)(colBase + b1_n + 64 * i) * ldb + kn + b1_k4);
            }
        }

#pragma unroll
        for (int kk = 0; kk < BK; kk += 8) {
            uint32_t af[MI][4], bf[NI][2];
            const int x = lq << 3;
#pragma unroll
            for (int mi = 0; mi < MI; mi++) {
                int m = wm * WM + mi * 16 + tm;
                af[mi][0] = As[(kk + lq)     * BM + ( m      ^ x)];
                af[mi][1] = As[(kk + lq)     * BM + ((m + 8) ^ x)];
                af[mi][2] = As[(kk + lq + 4) * BM + ( m      ^ x)];
                af[mi][3] = As[(kk + lq + 4) * BM + ((m + 8) ^ x)];
            }
#pragma unroll
            for (int ni = 0; ni < NI; ni++) {
                int n = wn * WN + ni * 8 + tm;
                bf[ni][0] = Bs[(kk + lq)     * BN + (n ^ x)];
                bf[ni][1] = Bs[(kk + lq + 4) * BN + (n ^ x)];
            }
#pragma unroll
            for (int mi = 0; mi < MI; mi++)
#pragma unroll
                for (int ni = 0; ni < NI; ni++)
                    mma_tf32(acc[mi][ni], af[mi][0], af[mi][1], af[mi][2], af[mi][3],
                             bf[ni][0], bf[ni][1]);
        }
        __syncthreads();
    }

    // epilogue
#pragma unroll
    for (int mi = 0; mi < MI; mi++) {
        int rBase = rowBase + wm * WM + mi * 16 + tm;
#pragma unroll
        for (int ni = 0; ni < NI; ni++) {
            int c = colBase + wn * WN + ni * 8 + 2 * lq;
#pragma unroll
            for (int half = 0; half < 2; half++) {
                int r = rBase + 8 * half;
                float2 v = make_float2(acc[mi][ni][2 * half], acc[mi][ni][2 * half + 1]);
                if (MODE == 0) {
                    v.x *= alpha; v.y *= alpha;
                    *(float2*)&C[(long long)r * ldc + c] = v;
                } else if (MODE == 2) {
                    v.x = (r == c     ? dval : 0.f) - v.x;
                    v.y = (r == c + 1 ? dval : 0.f) - v.y;
                    *(float2*)&C[(long long)r * ldc + c] = v;
                } else if (MODE == 3) {
                    *(float2*)&C[(long long)r * ldc + c] = v;
                    float2 v2;
                    v2.x = (r == c     ? dval : 0.f) - v.x;
                    v2.y = (r == c + 1 ? dval : 0.f) - v.y;
                    *(float2*)&C2[(long long)r * ldc + c] = v2;
                } else if (MODE == 4) {
                    v.x += bias[c]; v.y += bias[c + 1];
                    *(float2*)&C[(long long)r * ldc + c] = v;
                } else if (MODE == 5) {
                    int b = r >> 12, n = r & 4095;
                    int part = c >> 9, h = (c >> 6) & 7, d = c & 63;
                    if (part == 0) { v.x *= 0.125f; v.y *= 0.125f; }
                    float* dst = (part == 0) ? oq : ((part == 1) ? okk : ov);
                    *(float2*)&dst[((((long long)(b * 8 + h)) << 12) + n) * 64 + d] = v;
                } else { // 6
                    int b = bz >> 3, h = bz & 7;
                    *(float2*)&C[((long long)(b * 4096 + r)) * 512 + h * 64 + c] = v;
                }
            }
        }
    }
}

// ---------------- landmarks ---------------------------------------------------
__global__ void landmarks_kernel(const float* __restrict__ q, const float* __restrict__ k,
                                 float* __restrict__ qlm, float* __restrict__ klm)
{
    int idx = blockIdx.x;          // bh*256 + m
    int d = threadIdx.x;
    long long base = ((long long)idx * 16) * 64 + d;
    float sq = 0.f, sk = 0.f;
#pragma unroll
    for (int j = 0; j < 16; j++) {
        sq += q[base + j * 64];
        sk += k[base + j * 64];
    }
    qlm[(long long)idx * 64 + d] = sq * 0.0625f;
    klm[(long long)idx * 64 + d] = sk * 0.0625f;
}

// ---------------- softmaxes ----------------------------------------------------
__global__ void softmax256(float* __restrict__ data)
{
    long long row = (long long)blockIdx.x * 8 + (threadIdx.x >> 5);
    int lane = threadIdx.x & 31;
    float4* p = (float4*)(data + (row << 8));
    float4 a = p[lane], b = p[lane + 32];
    float m = fmaxf(fmaxf(fmaxf(a.x, a.y), fmaxf(a.z, a.w)),
                    fmaxf(fmaxf(b.x, b.y), fmaxf(b.z, b.w)));
#pragma unroll
    for (int s = 16; s; s >>= 1) m = fmaxf(m, __shfl_xor_sync(~0u, m, s));
    a.x = __expf(a.x - m); a.y = __expf(a.y - m); a.z = __expf(a.z - m); a.w = __expf(a.w - m);
    b.x = __expf(b.x - m); b.y = __expf(b.y - m); b.z = __expf(b.z - m); b.w = __expf(b.w - m);
    float sum = a.x + a.y + a.z + a.w + b.x + b.y + b.z + b.w;
#pragma unroll
    for (int s = 16; s; s >>= 1) sum += __shfl_xor_sync(~0u, sum, s);
    float inv = 1.f / sum;
    a.x *= inv; a.y *= inv; a.z *= inv; a.w *= inv;
    b.x *= inv; b.y *= inv; b.z *= inv; b.w *= inv;
    p[lane] = a; p[lane + 32] = b;
}

__global__ void softmax4096(float* __restrict__ data)
{
    __shared__ float redm[8], reds[8];
    float4* p = (float4*)(data + ((long long)blockIdx.x << 12));
    int tid = threadIdx.x;
    float4 v[4];
#pragma unroll
    for (int i = 0; i < 4; i++) v[i] = p[tid + 256 * i];
    float m = -3.4e38f;
#pragma unroll
    for (int i = 0; i < 4; i++)
        m = fmaxf(m, fmaxf(fmaxf(v[i].x, v[i].y), fmaxf(v[i].z, v[i].w)));
#pragma unroll
    for (int s = 16; s; s >>= 1) m = fmaxf(m, __shfl_xor_sync(~0u, m, s));
    if ((tid & 31) == 0) redm[tid >> 5] = m;
    __syncthreads();
#pragma unroll
    for (int j = 0; j < 8; j++) m = fmaxf(m, redm[j]);

    float sum = 0.f;
#pragma unroll
    for (int i = 0; i < 4; i++) {
        v[i].x = __expf(v[i].x - m); v[i].y = __expf(v[i].y - m);
        v[i].z = __expf(v[i].z - m); v[i].w = __expf(v[i].w - m);
        sum += v[i].x + v[i].y + v[i].z + v[i].w;
    }
#pragma unroll
    for (int s = 16; s; s >>= 1) sum += __shfl_xor_sync(~0u, sum, s);
    if ((tid & 31) == 0) reds[tid >> 5] = sum;
    __syncthreads();
    sum = 0.f;
#pragma unroll
    for (int j = 0; j < 8; j++) sum += reds[j];
    float inv = 1.f / sum;
#pragma unroll
    for (int i = 0; i < 4; i++) {
        v[i].x *= inv; v[i].y *= inv; v[i].z *= inv; v[i].w *= inv;
        p[tid + 256 * i] = v[i];
    }
}

// ---------------- pinv init ----------------------------------------------------
__global__ void zero_gmax(float* gm) { gm[0] = 0.f; gm[1] = 0.f; }

__global__ void pinv_scales(const float* __restrict__ a, float* gm)
{
    __shared__ float red[256];
    int bh = blockIdx.x, tid = threadIdx.x;
    const float* A = a + ((long long)bh << 16);
    float rs = 0.f;
    for (int j = 0; j < 256; j++) rs += fabsf(A[tid * 256 + j]);
    red[tid] = rs; __syncthreads();
    for (int s = 128; s > 0; s >>= 1) {
        if (tid < s) red[tid] = fmaxf(red[tid], red[tid + s]);
        __syncthreads();
    }
    if (tid == 0) atomicMax((int*)&gm[0], __float_as_int(red[0]));
    __syncthreads();
    float cs = 0.f;
    for (int i = 0; i < 256; i++) cs += fabsf(A[i * 256 + tid]);
    red[tid] = cs; __syncthreads();
    for (int s = 128; s > 0; s >>= 1) {
        if (tid < s) red[tid] = fmaxf(red[tid], red[tid + s]);
        __syncthreads();
    }
    if (tid == 0) atomicMax((int*)&gm[1], __float_as_int(red[0]));
}

__global__ void pinv_init(const float* __restrict__ a, float* __restrict__ z,
                          const float* __restrict__ gm)
{
    long long t = (long long)blockIdx.x * 256 + threadIdx.x;
    int bh = (int)(t >> 16);
    int ij = (int)(t & 65535);
    int i = ij >> 8, j = ij & 255;
    float inv = 1.f / (gm[0] * gm[1]);
    z[((long long)bh << 16) + ij] = a[((long long)bh << 16) + (j << 8) + i] * inv;
}

// ---------------- depthwise conv, accumulates into 'of' layout ------------------
__global__ void conv_add_of(const float* __restrict__ v, const float* __restrict__ w,
                            float* __restrict__ of)
{
    long long t = (long long)blockIdx.x * 256 + threadIdx.x;   // BH*N*DH
    int d = (int)(t & 63);
    long long r = t >> 6;
    int n  = (int)(r & 4095);
    int bh = (int)(r >> 12);
    int h  = bh & 7, b = bh >> 3;
    const float* vp = v + ((long long)bh << 18) + d;
    float s = 0.f;
#pragma unroll
    for (int tp = 0; tp < 33; tp++) {
        int nn = n + tp - 16;
        if (nn >= 0 && nn < 4096)
            s = fmaf(vp[(long long)nn << 6], w[h * 33 + tp], s);
    }
    of[((long long)(b * 4096 + n)) * 512 + h * 64 + d] += s;
}

// ---------------- host orchestration -------------------------------------------
extern "C" void kernel_launch(void* const* d_in, const int* in_sizes, int n_in,
                              void* d_out, int out_size)
{
    const float* x    = (const float*)d_in[0];
    const float* Wqkv = (const float*)d_in[1];
    const float* Wout = (const float*)d_in[2];
    const float* bout = (const float*)d_in[3];
    const float* rk   = (const float*)d_in[4];
    float* yout = (float*)d_out;

    float *q, *k, *v, *qlm, *klm, *s1, *a2, *s3, *z, *z2, *xz, *t1, *t3, *t5,
          *a3v, *zv, *of, *gm;
    cudaGetSymbolAddress((void**)&q,   g_q);
    cudaGetSymbolAddress((void**)&k,   g_k);
    cudaGetSymbolAddress((void**)&v,   g_v);
    cudaGetSymbolAddress((void**)&qlm, g_qlm);
    cudaGetSymbolAddress((void**)&klm, g_klm);
    cudaGetSymbolAddress((void**)&s1,  g_s1);
    cudaGetSymbolAddress((void**)&a2,  g_a2);
    cudaGetSymbolAddress((void**)&s3,  g_s3);
    cudaGetSymbolAddress((void**)&z,   g_z);
    cudaGetSymbolAddress((void**)&z2,  g_z2);
    cudaGetSymbolAddress((void**)&xz,  g_xz);
    cudaGetSymbolAddress((void**)&t1,  g_t1);
    cudaGetSymbolAddress((void**)&t3,  g_t3);
    cudaGetSymbolAddress((void**)&t5,  g_t5);
    cudaGetSymbolAddress((void**)&a3v, g_a3v);
    cudaGetSymbolAddress((void**)&zv,  g_zv);
    cudaGetSymbolAddress((void**)&of,  g_of);
    cudaGetSymbolAddress((void**)&gm,  g_gmax);

    const long long sQ  = (long long)N_ * DH_;   // 262144
    const long long sLM = (long long)M_ * DH_;   // 16384
    const long long sS1 = (long long)N_ * M_;    // 1048576
    const long long sMM = (long long)M_ * M_;    // 65536

    // 1. qkv projection with scatter (q scaled)
    gemm_tc<128,128,2,4,0,5><<<dim3(12, 128, 1), 256>>>(
        512, x, 512, 0, Wqkv, 1536, 0,
        nullptr, 0, 0, 1.f, 0.f, nullptr, nullptr, q, k, v);

    // 2. landmarks
    landmarks_kernel<<<BH_ * M_, DH_>>>(q, k, qlm, klm);

    // 3. sim1 = q @ klm^T ; softmax (rows of 256)
    gemm_tc<128,128,2,4,1,0><<<dim3(2, 32, BH_), 256>>>(
        64, q, 64, sQ, klm, 64, sLM,
        s1, 256, sS1, 1.f, 0.f, nullptr, nullptr, nullptr, nullptr, nullptr);
    softmax256<<<(BH_ * N_) / 8, 256>>>(s1);

    // 4. sim2 = qlm @ klm^T ; softmax -> attn2
    gemm_tc<128,128,2,4,1,0><<<dim3(2, 2, BH_), 256>>>(
        64, qlm, 64, sLM, klm, 64, sLM,
        a2, 256, sMM, 1.f, 0.f, nullptr, nullptr, nullptr, nullptr, nullptr);
    softmax256<<<(BH_ * M_) / 8, 256>>>(a2);

    // 5. sim3 = qlm @ k^T ; softmax (rows of 4096)
    gemm_tc<128,128,2,4,1,0><<<dim3(32, 2, BH_), 256>>>(
        64, qlm, 64, sLM, k, 64, sQ,
        s3, 4096, (long long)M_ * N_, 1.f, 0.f, nullptr, nullptr, nullptr, nullptr, nullptr);
    softmax4096<<<BH_ * M_, 256>>>(s3);

    // 6. pinv init
    zero_gmax<<<1, 1>>>(gm);
    pinv_scales<<<BH_, 256>>>(a2, gm);
    pinv_init<<<(BH_ * M_ * M_) / 256, 256>>>(a2, z, gm);

    // 7. Newton-Schulz x6
    float* za = z;
    float* zb = z2;
    for (int it = 0; it < 6; it++) {
        gemm_tc<128,128,2,4,0,3><<<dim3(2, 2, BH_), 256>>>(
            256, a2, 256, sMM, za, 256, sMM,
            xz, 256, sMM, 1.f, 7.f, t1, nullptr, nullptr, nullptr, nullptr);
        gemm_tc<128,128,2,4,0,2><<<dim3(2, 2, BH_), 256>>>(
            256, xz, 256, sMM, t1, 256, sMM,
            t3, 256, sMM, 1.f, 15.f, nullptr, nullptr, nullptr, nullptr, nullptr);
        gemm_tc<128,128,2,4,0,2><<<dim3(2, 2, BH_), 256>>>(
            256, xz, 256, sMM, t3, 256, sMM,
            t5, 256, sMM, 1.f, 13.f, nullptr, nullptr, nullptr, nullptr, nullptr);
        gemm_tc<128,128,2,4,0,0><<<dim3(2, 2, BH_), 256>>>(
            256, za, 256, sMM, t5, 256, sMM,
            zb, 256, sMM, 0.25f, 0.f, nullptr, nullptr, nullptr, nullptr, nullptr);
        float* sw = za; za = zb; zb = sw;
    }

    // 8. a3v = attn3 @ v   [256 x 64], K=4096
    gemm_tc<128,64,4,2,0,0><<<dim3(1, 2, BH_), 256>>>(
        4096, s3, 4096, (long long)M_ * N_, v, 64, sQ,
        a3v, 64, sLM, 1.f, 0.f, nullptr, nullptr, nullptr, nullptr, nullptr);

    // 9. zv = z @ a3v   [256 x 64], K=256
    gemm_tc<128,64,4,2,0,0><<<dim3(1, 2, BH_), 256>>>(
        256, za, 256, sMM, a3v, 64, sLM,
        zv, 64, sLM, 1.f, 0.f, nullptr, nullptr, nullptr, nullptr, nullptr);

    // 10. out = attn1 @ zv  -> writes 'of' [b,n,h,d] directly
    gemm_tc<128,64,4,2,0,6><<<dim3(1, 32, BH_), 256>>>(
        256, s1, 256, sS1, zv, 64, sLM,
        of, 0, 0, 1.f, 0.f, nullptr, nullptr, nullptr, nullptr, nullptr);

    // 11. += depthwise conv of v (into 'of' layout)
    conv_add_of<<<(BH_ * N_ * DH_) / 256, 256>>>(v, rk, of);

    // 12. final projection: y = of @ Wout + bout
    gemm_tc<128,128,2,4,0,4><<<dim3(4, 128, 1), 256>>>(
        512, of, 512, 0, Wout, 512, 0,
        yout, 512, 0, 1.f, 0.f, nullptr, bout, nullptr, nullptr, nullptr);
}